// round 10
// baseline (speedup 1.0000x reference)
#include <cuda_runtime.h>
#include <cuda_bf16.h>

#define FRAME_L   1024
#define HOP       256
#define SWIN      1792   // staged wav window: frames B-3..B -> 7*256 + 768 = 1792 floats

// ---------------------------------------------------------------------------
// Compile-time half-Hann table: g_hh.v[i] = 0.5 * (0.5 - 0.5*cos(2*pi*i/1024))
// (pre-halved: interior path needs no normalization; edge ratio acc/ws is
// invariant under joint halving)
// ---------------------------------------------------------------------------
struct alignas(16) HannTab { float v[FRAME_L]; };

constexpr double kPI = 3.141592653589793238462643383279502884;

constexpr double ccos_core(double x) {   // |x| <= pi/2, Taylor, err < 1e-16
    double x2 = x * x, s = 1.0, term = 1.0;
    for (int k = 1; k <= 10; k++) { term *= -x2 / (double)((2*k-1)*(2*k)); s += term; }
    return s;
}
constexpr double ccos(double x) {        // x in [0, 2*pi)
    if (x > kPI) x = 2.0 * kPI - x;
    if (x > 0.5 * kPI) return -ccos_core(kPI - x);
    return ccos_core(x);
}
constexpr HannTab make_half_hann() {
    HannTab t{};
    for (int i = 0; i < FRAME_L; i++) {
        double th = (2.0 * kPI * (double)i) / (double)FRAME_L;
        t.v[i] = (float)(0.5 * (0.5 - 0.5 * ccos(th)));
    }
    return t;
}
__device__ constexpr HannTab g_hh = make_half_hann();

// ---------------------------------------------------------------------------
// One sample per thread; block of 256 covers t in [256*B, 256*B+256), so
// fmax == blockIdx.x for every thread (all frame logic block-uniform).
// The block's 4 covering frames live entirely in wav[(B-3)*256, B*256+1024)
// = 1792 floats, staged coalesced into smem; gathers become LDS with lane
// stride `scale` floats (vs 4*scale-stride LDG before -> ~4x fewer l1tex
// wavefronts on the gather path).
//
// Invalid/unvoiced frames use {scale=1, nlen=1024}: the resample path then
// reproduces passthrough EXACTLY in fp32 (x=(j+0.5)-0.5=j, w=0) -> datapath
// is branch-free.
// ---------------------------------------------------------------------------
__global__ void __launch_bounds__(256)
psola_kernel(const float* __restrict__ wav,
             const float* __restrict__ src_f0,
             const float* __restrict__ tgt_f0,
             const int*   __restrict__ voiced,
             float* __restrict__ out,
             int T, int nf)
{
    __shared__ float  s_wav[SWIN];
    __shared__ float2 s_par[4];      // frames B-3 .. B  (slot = f - (B-3))

    const int B    = (int)blockIdx.x;         // == fmax for all threads
    const int tid  = (int)threadIdx.x;
    const int base = (B - 3) * HOP;           // wav index of s_wav[0] (may be <0)

    // Stage the 1792-float window, coalesced (7 iters/thread).
    #pragma unroll
    for (int i = tid; i < SWIN; i += 256) {
        int g = base + i;
        s_wav[i] = (g >= 0 && g < T) ? wav[g] : 0.0f;
    }

    // Threads 0..3 compute frame params (IEEE divide, must match jnp fp32).
    if (tid < 4) {
        int f = (B - 3) + tid;
        float2 p = make_float2(1.0f, (float)FRAME_L);
        if (f >= 0 && f < nf) {
            float s = src_f0[f];
            float t = tgt_f0[f];
            if ((voiced[f] != 0) && (s >= 1.0f) && (t >= 1.0f)) {
                float ratio = fminf(fmaxf(s / t, 0.25f), 4.0f);
                float nl = fmaxf(1.0f, rintf((float)FRAME_L * ratio));
                p = make_float2((float)FRAME_L / nl, nl);
            }
        }
        s_par[tid] = p;
    }
    __syncthreads();

    int t = (B << 8) + tid;
    if (t >= T) return;

    const bool interior = (B >= 3) & (B <= nf - 1);   // block-uniform

    float acc = 0.0f;
    float ws  = 0.0f;                 // edge blocks only (half-hann sums)
    float jh  = (float)tid + 0.5f;    // j + 0.5 at k=0 (exact)

    #pragma unroll
    for (int k = 0; k < 4; k++) {
        int f = B - k;
        if (!interior) {
            if (f < 0 || f >= nf) continue;
        }

        float2 p     = s_par[3 - k];
        float  scale = p.x;
        int    j     = tid + (k << 8);
        const float* fr = s_wav + ((3 - k) << 8);     // frame start in smem

        float hw = __ldg(g_hh.v + j);                 // 1 line per warp
        if (!interior) ws += hw;

        float x  = fmaxf(fmaf(jh + (float)(k << 8), scale, -0.5f), 0.0f);
        int   x0 = min(__float2int_rd(x), FRAME_L - 2);
        float w  = x - (float)x0;
        float a  = fr[x0];
        float b  = fr[x0 + 1];                        // same LDS base, +4 imm
        float v  = fmaf(b - a, w, a);
        float c  = ((float)j < p.y) ? v : 0.0f;
        acc = fmaf(c, hw, acc);
    }

    float r;
    if (interior) {
        r = acc;                       // quadrature hann phases sum to 2; table pre-halved
    } else {
        r = (ws > 1e-8f) ? acc / ws : acc;
    }
    out[t] = r;
}

extern "C" void kernel_launch(void* const* d_in, const int* in_sizes, int n_in,
                              void* d_out, int out_size)
{
    const float* wav    = (const float*)d_in[0];
    const float* src_f0 = (const float*)d_in[1];
    const float* tgt_f0 = (const float*)d_in[2];
    const int*   voiced = (const int*)d_in[3];
    float* out = (float*)d_out;

    int T  = in_sizes[0];
    int nf_cap = (T - FRAME_L) / HOP + 1;
    int nf = in_sizes[1] < nf_cap ? in_sizes[1] : nf_cap;

    int blocks = (T + 255) / 256;
    psola_kernel<<<blocks, 256>>>(wav, src_f0, tgt_f0, voiced, out, T, nf);
}